// round 16
// baseline (speedup 1.0000x reference)
#include <cuda_runtime.h>
#include <cuda_fp16.h>
#include <math.h>
#include <cstdint>

// ---------------------------------------------------------------------------
// Scratch
// ---------------------------------------------------------------------------
#define C0_OFF   0u
#define C1_OFF   6291456u
#define C2_OFF   7864320u
#define C3_OFF   8257536u
#define HI_OFF   8355840u                 // ushort[64*64*256] (hi, fp16)
#define HJ_OFF   9404416u                 // ushort[64*64*256] (hj, fp16)
#define SP_OFF   10452992u                // 4096*256 floats
#define WP_OFF   11501568u                // fp16 blob: 24*8192 ushorts = 384KB
#define SCRATCH_TOTAL 11698176u

__device__ float g_scratch[SCRATCH_TOTAL];

// ---------------------------------------------------------------------------
// Helpers
// ---------------------------------------------------------------------------
__device__ __forceinline__ uint32_t smem_u32(const void* p) {
    uint32_t a;
    asm("{ .reg .u64 t; cvta.to.shared.u64 t, %1; cvt.u32.u64 %0, t; }" : "=r"(a) : "l"(p));
    return a;
}

__device__ __forceinline__ void mma_f16(float& d0, float& d1, float& d2, float& d3,
                                        uint32_t a0, uint32_t a1, uint32_t a2, uint32_t a3,
                                        uint32_t b0, uint32_t b1) {
    asm volatile(
        "mma.sync.aligned.m16n8k16.row.col.f32.f16.f16.f32 "
        "{%0,%1,%2,%3},{%4,%5,%6,%7},{%8,%9},{%0,%1,%2,%3};"
        : "+f"(d0), "+f"(d1), "+f"(d2), "+f"(d3)
        : "r"(a0), "r"(a1), "r"(a2), "r"(a3), "r"(b0), "r"(b1));
}

#define LDSM_X4(r, addr) \
    asm volatile("ldmatrix.sync.aligned.m8n8.x4.shared.b16 {%0,%1,%2,%3}, [%4];" \
        : "=r"((r)[0]), "=r"((r)[1]), "=r"((r)[2]), "=r"((r)[3]) : "r"(addr))

// pack: low half = f16(v0), high half = f16(v1)
__device__ __forceinline__ uint32_t packh(float v0, float v1) {
    uint32_t r;
    asm("cvt.rn.f16x2.f32 %0, %1, %2;" : "=r"(r) : "f"(v1), "f"(v0));
    return r;
}

__device__ __forceinline__ uint32_t hadd2_relu(uint32_t a, uint32_t b) {
    uint32_t r;
    asm("{ .reg .b32 t; add.f16x2 t, %1, %2; max.f16x2 %0, t, %3; }"
        : "=r"(r) : "r"(a), "r"(b), "r"(0u));
    return r;
}

#define CP_ASYNC16(dst, src) \
    asm volatile("cp.async.cg.shared.global [%0], [%1], 16;" :: "r"(dst), "l"(src) : "memory")
#define CP_COMMIT() asm volatile("cp.async.commit_group;" ::: "memory")

// ---------------------------------------------------------------------------
// Slab-parallel Conv + BN + ReLU (R14 proven: static smem, R12/R14 configs)
// ---------------------------------------------------------------------------
template<int CIN, int W, int RPB, int CPT>
__global__ void __launch_bounds__(24 * RPB * (W / CPT)) conv_slab_kernel(
    const float* __restrict__ in, const float* __restrict__ w,
    const float* __restrict__ bns, const float* __restrict__ bnb,
    float* __restrict__ out, int Hin)
{
    constexpr int NT = 24 * RPB * (W / CPT);
    constexpr int R  = 2 * RPB + 1;
    constexpr int C  = 2 * W + 1;
    constexpr int Cp = 2 * W + 2;

    __shared__ float in_s[CIN * R * Cp];
    __shared__ float w_s[9 * CIN * 24];

    int t = threadIdx.x;
    constexpr int SLABS = W / RPB;
    int n    = blockIdx.x / SLABS;
    int slab = blockIdx.x % SLABS;
    int co   = t % 24;
    int rest = t / 24;
    int tcol = rest % (W / CPT);
    int orow = rest / (W / CPT);

    for (int l = t; l < 9 * CIN * 24; l += NT) w_s[l] = w[l];

    int ih0 = slab * RPB * 2 - 1;
    for (int l = t; l < CIN * R * C; l += NT) {
        int ci  = l / (R * C);
        int rem = l % (R * C);
        int r = rem / C, c = rem % C;
        int ih = ih0 + r, iw = c - 1;
        float v = 0.f;
        if (ih >= 0 && ih < Hin && iw >= 0 && iw < Hin)
            v = in[((n * CIN + ci) * Hin + ih) * Hin + iw];
        in_s[ci * (R * Cp) + r * Cp + c] = v;
    }
    __syncthreads();

    float acc[CPT];
#pragma unroll
    for (int o = 0; o < CPT; o++) acc[o] = 0.f;

#pragma unroll 2
    for (int ci = 0; ci < CIN; ci++) {
        float wr[9];
#pragma unroll
        for (int k = 0; k < 9; k++) wr[k] = w_s[k * (CIN * 24) + ci * 24 + co];
#pragma unroll
        for (int kh = 0; kh < 3; kh++) {
            const float* row = &in_s[ci * (R * Cp) + (orow * 2 + kh) * Cp + tcol * CPT * 2];
#pragma unroll
            for (int o = 0; o < CPT; o++) {
                acc[o] += wr[kh * 3 + 0] * row[2 * o];
                acc[o] += wr[kh * 3 + 1] * row[2 * o + 1];
                acc[o] += wr[kh * 3 + 2] * row[2 * o + 2];
            }
        }
    }

    float sc = bns[co], bb = bnb[co];
#pragma unroll
    for (int o = 0; o < CPT; o++) {
        float v = fmaxf(acc[o] * sc + bb, 0.f);
        out[((n * 24 + co) * W + slab * RPB + orow) * W + tcol * CPT + o] = v;
    }
}

// ---------------------------------------------------------------------------
// g layer 1: grid 256 (4 blocks per n, 16 p rows each). hi AND hj as fp16.
// ---------------------------------------------------------------------------
__global__ void __launch_bounds__(256) g1_kernel(
    const float* __restrict__ c3, const float* __restrict__ qst,
    const float* __restrict__ gw1, const float* __restrict__ gb1,
    unsigned short* __restrict__ hih, unsigned short* __restrict__ hjh)
{
    __shared__ float xs[64 * 26];
    __shared__ float qs[128];
    int n = blockIdx.x >> 2, pg = blockIdx.x & 3;
    int t = threadIdx.x;

    for (int l = t; l < 64 * 26; l += 256) {
        int p = l / 26, c = l % 26;
        int h = p >> 3, w = p & 7;
        float v;
        if (c < 24)       v = c3[((n * 24 + c) * 8 + h) * 8 + w];
        else if (c == 24) v = -1.f + (2.f / 7.f) * (float)w;
        else              v = -1.f + (2.f / 7.f) * (float)h;
        xs[l] = v;
    }
    if (t < 128) qs[t] = qst[n * 128 + t];
    __syncthreads();

    int o = t;
    float wa[26], wb[26];
#pragma unroll
    for (int c = 0; c < 26; c++) {
        wa[c] = gw1[c * 256 + o];
        wb[c] = gw1[(26 + c) * 256 + o];
    }
    float hq = gb1[o];
    for (int k = 0; k < 128; k++) hq += qs[k] * gw1[(52 + k) * 256 + o];

    for (int p = pg * 16; p < pg * 16 + 16; p++) {
        float ai = hq, bj = 0.f;
#pragma unroll
        for (int c = 0; c < 26; c++) {
            float x = xs[p * 26 + c];
            ai += x * wa[c];
            bj += x * wb[c];
        }
        __half ha = __float2half(ai);
        __half hb = __float2half(bj);
        hih[(n * 64 + p) * 256 + o] = *(unsigned short*)&ha;
        hjh[(n * 64 + p) * 256 + o] = *(unsigned short*)&hb;
    }
}

// ---------------------------------------------------------------------------
// Weight prep (R11 proven): stride-16 + XOR-swizzled fp16 blob.
// ---------------------------------------------------------------------------
__global__ void __launch_bounds__(256) prep_w_kernel(
    const float* __restrict__ w2, const float* __restrict__ w3,
    const float* __restrict__ w4, unsigned short* __restrict__ blob)
{
    int idx = blockIdx.x * 256 + threadIdx.x;      // 0..196607
    int l = idx >> 16;
    int rem = idx & 65535;
    int k = rem >> 8, n = rem & 255;
    const float* W = (l == 0) ? w2 : ((l == 1) ? w3 : w4);
    __half wh = __float2half(W[k * 256 + n]);

    int c   = k >> 5;
    int k2c = (k >> 1) & 15;
    int s   = k2c >> 3;
    int wi  = k2c & 7;
    int tt  = wi & 3;
    int j   = wi >> 2;
    int pos = tt * 4 + ((s ^ ((n >> 1) & 1)) * 2) + j;
    int gc  = l * 8 + c;
    blob[(size_t)gc * 8192 + (n * 16 + pos) * 2 + (k & 1)] = *(unsigned short*)&wh;
}

// ---------------------------------------------------------------------------
// fp16 mma relation MLP — R12 smem layout (71.7KB) + minBlocks=3 for
// 3 blocks/SM occupancy. Block = 64 pairs, 256 threads = 8 warps.
// Warp tile 32M x 64N. A via ldmatrix.x4; B via conflict-free uint2.
// SMEM words: A[0,8448) WB0[8448,12544) WB1[12544,16640)
//             bias[16640,17408) red[17408,17920)  -> 71680 bytes
// ---------------------------------------------------------------------------
extern __shared__ uint32_t smw[];

__device__ __forceinline__ void issue_chunk(const char* __restrict__ blob,
                                            uint32_t wsm, int gc, int tid)
{
    const char* src = blob + (size_t)gc * 16384;
#pragma unroll
    for (int r = 0; r < 4; r++) {
        int op = r * 256 + tid;          // 0..1023, linear 16KB copy
        CP_ASYNC16(wsm + (uint32_t)(op * 16), src + op * 16);
    }
    CP_COMMIT();
}

__global__ void __launch_bounds__(256, 3) rn_g_mma(
    const unsigned short* __restrict__ hih, const unsigned short* __restrict__ hjh,
    const unsigned short* __restrict__ wblob,
    const float* __restrict__ b2, const float* __restrict__ b3,
    const float* __restrict__ b4, float* __restrict__ spart)
{
    const char* blob = (const char*)wblob;
    int tid = threadIdx.x;
    int wid = tid >> 5, lane = tid & 31;
    int g = lane >> 2, t = lane & 3;
    int wm = wid & 1, wn = wid >> 1;
    uint32_t xg = (uint32_t)((g >> 1) & 1) << 1;   // B s-XOR offset (words)

    float* biasf = (float*)&smw[16640];
    float* red   = (float*)&smw[17408];
    uint32_t sb = smem_u32(smw);
    uint32_t wsm0 = sb + 33792u;
    uint32_t wsm1 = sb + 50176u;

    biasf[tid]       = b2[tid];
    biasf[256 + tid] = b3[tid];
    biasf[512 + tid] = b4[tid];

    issue_chunk(blob, wsm0, 0, tid);

    // ---- L0: A = relu2(hi + hj), both fp16 in gmem
    int nb = blockIdx.x >> 6;
    int ii = blockIdx.x & 63;
    {
        int m = tid >> 2, q = tid & 3;
        const uint32_t* hir = (const uint32_t*)(hih + (size_t)(nb * 64 + ii) * 256) + q * 32;
        const uint32_t* hjr = (const uint32_t*)(hjh + (size_t)(nb * 64 + m) * 256) + q * 32;
        int base = m * 132 + q * 32;
#pragma unroll 8
        for (int w = 0; w < 32; w++)
            smw[base + w] = hadd2_relu(hir[w], hjr[w]);
    }

    float acc[2][8][4];
    uint32_t abase0 = sb + (uint32_t)(((wm * 32 + (lane & 15)) * 132 + ((lane >> 4) << 2)) * 4);
    uint32_t abase1 = abase0 + 16u * 132u * 4u;

#pragma unroll 1
    for (int l = 0; l < 3; l++) {
#pragma unroll
        for (int mt = 0; mt < 2; mt++)
#pragma unroll
            for (int nt = 0; nt < 8; nt++)
#pragma unroll
                for (int q = 0; q < 4; q++) acc[mt][nt][q] = 0.f;

#pragma unroll 1
        for (int c = 0; c < 8; c++) {
            int gc = l * 8 + c;
            asm volatile("cp.async.wait_group 0;" ::: "memory");
            __syncthreads();
            if (gc < 23)
                issue_chunk(blob, ((gc + 1) & 1) ? wsm1 : wsm0, gc + 1, tid);

            uint32_t wbw = 8448u + (uint32_t)(gc & 1) * 4096u;
            uint32_t coff = (uint32_t)c * 64u;

            // s-step inner structure: keep only one s-step's fragments live
#pragma unroll
            for (int s = 0; s < 2; s++) {
                uint32_t afr0[4], afr1[4];
                LDSM_X4(afr0, abase0 + coff + (uint32_t)s * 32u);
                LDSM_X4(afr1, abase1 + coff + (uint32_t)s * 32u);
                uint32_t soff = ((uint32_t)s << 1) ^ xg;
#pragma unroll
                for (int nt = 0; nt < 8; nt++) {
                    uint32_t wofs = wbw + (uint32_t)(((wn * 64 + nt * 8 + g) << 4) + (t << 2)) + soff;
                    uint2 B = *(const uint2*)&smw[wofs];
                    mma_f16(acc[0][nt][0], acc[0][nt][1], acc[0][nt][2], acc[0][nt][3],
                            afr0[0], afr0[1], afr0[2], afr0[3], B.x, B.y);
                    mma_f16(acc[1][nt][0], acc[1][nt][1], acc[1][nt][2], acc[1][nt][3],
                            afr1[0], afr1[1], afr1[2], afr1[3], B.x, B.y);
                }
            }
        }
        __syncthreads();   // all MMA reads of A done before epilogue overwrites A

        if (l < 2) {
#pragma unroll
            for (int mt = 0; mt < 2; mt++)
#pragma unroll
                for (int nt = 0; nt < 8; nt++) {
                    int n0 = wn * 64 + nt * 8 + 2 * t;
                    float2 bv = *(const float2*)&biasf[l * 256 + n0];
                    int nh = n0 >> 1;
                    int rbase = (wm * 32 + mt * 16 + g) * 132;
                    smw[rbase + nh] =
                        packh(fmaxf(acc[mt][nt][0] + bv.x, 0.f),
                              fmaxf(acc[mt][nt][1] + bv.y, 0.f));
                    smw[rbase + 1056 + nh] =
                        packh(fmaxf(acc[mt][nt][2] + bv.x, 0.f),
                              fmaxf(acc[mt][nt][3] + bv.y, 0.f));
                }
        } else {
#pragma unroll
            for (int nt = 0; nt < 8; nt++) {
                int n0 = wn * 64 + nt * 8 + 2 * t;
                float2 bv = *(const float2*)&biasf[512 + n0];
                float cs0 = fmaxf(acc[0][nt][0] + bv.x, 0.f) + fmaxf(acc[0][nt][2] + bv.x, 0.f)
                          + fmaxf(acc[1][nt][0] + bv.x, 0.f) + fmaxf(acc[1][nt][2] + bv.x, 0.f);
                float cs1 = fmaxf(acc[0][nt][1] + bv.y, 0.f) + fmaxf(acc[0][nt][3] + bv.y, 0.f)
                          + fmaxf(acc[1][nt][1] + bv.y, 0.f) + fmaxf(acc[1][nt][3] + bv.y, 0.f);
#pragma unroll
                for (int off = 16; off >= 4; off >>= 1) {
                    cs0 += __shfl_xor_sync(0xffffffffu, cs0, off);
                    cs1 += __shfl_xor_sync(0xffffffffu, cs1, off);
                }
                if (g == 0) {
                    red[wm * 256 + n0] = cs0;
                    red[wm * 256 + n0 + 1] = cs1;
                }
            }
            __syncthreads();
            float s = red[tid] + red[256 + tid];
            spart[(size_t)blockIdx.x * 256 + tid] = s;
        }
    }
}

// ---------------------------------------------------------------------------
// Reduce 64 partials per n, f-MLP + classifier + log_softmax (R13 version)
// ---------------------------------------------------------------------------
__global__ void __launch_bounds__(512) f_kernel(
    const float* __restrict__ spart,
    const float* __restrict__ fw1, const float* __restrict__ fb1,
    const float* __restrict__ fw2, const float* __restrict__ fb2,
    const float* __restrict__ cw,  const float* __restrict__ cb,
    float* __restrict__ out)
{
    __shared__ float a[256], b[256], part[512];
    int n = blockIdx.x, t = threadIdx.x;
    int hf = t >> 8, o = t & 255;

    const float* sp = spart + (size_t)(n * 64) * 256 + o;
    float v = 0.f;
    for (int i = hf * 32; i < hf * 32 + 32; i++) v += sp[i * 256];
    part[t] = v;
    __syncthreads();
    if (t < 256) a[t] = part[t] + part[t + 256];
    __syncthreads();

    float acc = 0.f;
    for (int k = 0; k < 128; k++)
        acc += a[hf * 128 + k] * fw1[(hf * 128 + k) * 256 + o];
    part[t] = acc;
    __syncthreads();
    if (t < 256) b[t] = fmaxf(part[t] + part[t + 256] + fb1[t], 0.f);
    __syncthreads();

    acc = 0.f;
    for (int k = 0; k < 128; k++)
        acc += b[hf * 128 + k] * fw2[(hf * 128 + k) * 256 + o];
    part[t] = acc;
    __syncthreads();
    if (t < 256) a[t] = fmaxf(part[t] + part[t + 256] + fb2[t], 0.f);
    __syncthreads();

    if (t < 32) {
        float lg = cb[t];
        for (int k = 0; k < 256; k++) lg += a[k] * cw[k * 32 + t];
        float mx = lg;
#pragma unroll
        for (int off = 16; off; off >>= 1)
            mx = fmaxf(mx, __shfl_xor_sync(0xffffffffu, mx, off));
        float e = expf(lg - mx);
        float se = e;
#pragma unroll
        for (int off = 16; off; off >>= 1)
            se += __shfl_xor_sync(0xffffffffu, se, off);
        out[(n << 5) + t] = lg - mx - logf(se);
    }
}

// ---------------------------------------------------------------------------
// Launch
// ---------------------------------------------------------------------------
extern "C" void kernel_launch(void* const* d_in, const int* in_sizes, int n_in,
                              void* d_out, int out_size)
{
    const float* img  = (const float*)d_in[0];
    const float* qst  = (const float*)d_in[1];
    const float* cw0  = (const float*)d_in[2];
    const float* cw1  = (const float*)d_in[3];
    const float* cw2  = (const float*)d_in[4];
    const float* cw3  = (const float*)d_in[5];
    const float* bs0  = (const float*)d_in[6];
    const float* bb0  = (const float*)d_in[7];
    const float* bs1  = (const float*)d_in[8];
    const float* bb1  = (const float*)d_in[9];
    const float* bs2  = (const float*)d_in[10];
    const float* bb2  = (const float*)d_in[11];
    const float* bs3  = (const float*)d_in[12];
    const float* bb3  = (const float*)d_in[13];
    const float* gw1  = (const float*)d_in[14];
    const float* gb1  = (const float*)d_in[15];
    const float* gw2  = (const float*)d_in[16];
    const float* gb2  = (const float*)d_in[17];
    const float* gw3  = (const float*)d_in[18];
    const float* gb3  = (const float*)d_in[19];
    const float* gw4  = (const float*)d_in[20];
    const float* gb4  = (const float*)d_in[21];
    const float* fw1  = (const float*)d_in[22];
    const float* fb1  = (const float*)d_in[23];
    const float* fw2  = (const float*)d_in[24];
    const float* fb2  = (const float*)d_in[25];
    const float* clw  = (const float*)d_in[26];
    const float* clb  = (const float*)d_in[27];
    float* out = (float*)d_out;

    void* base_v = nullptr;
    cudaGetSymbolAddress(&base_v, g_scratch);
    float* base = (float*)base_v;
    float* c0 = base + C0_OFF;
    float* c1 = base + C1_OFF;
    float* c2 = base + C2_OFF;
    float* c3 = base + C3_OFF;
    unsigned short* hih = (unsigned short*)(base + HI_OFF);
    unsigned short* hjh = (unsigned short*)(base + HJ_OFF);
    float* sp = base + SP_OFF;
    unsigned short* wp = (unsigned short*)(base + WP_OFF);

    cudaFuncSetAttribute(rn_g_mma, cudaFuncAttributeMaxDynamicSharedMemorySize, 71680);

    prep_w_kernel<<<768, 256>>>(gw2, gw3, gw4, wp);

    // R14 proven conv configs (grids stay large)
    conv_slab_kernel<3, 64, 1, 8><<<4096, 192>>>(img, cw0, bs0, bb0, c0, 128);
    conv_slab_kernel<24, 32, 1, 4><<<2048, 192>>>(c0, cw1, bs1, bb1, c1, 64);
    conv_slab_kernel<24, 16, 2, 4><<<512, 192>>>(c1, cw2, bs2, bb2, c2, 32);
    conv_slab_kernel<24, 8, 4, 4><<<128, 192>>>(c2, cw3, bs3, bb3, c3, 16);

    g1_kernel<<<256, 256>>>(c3, qst, gw1, gb1, hih, hjh);

    rn_g_mma<<<4096, 256, 71680>>>(hih, hjh, wp, gb2, gb3, gb4, sp);

    f_kernel<<<64, 512>>>(sp, fw1, fb1, fw2, fb2, clw, clb, out);
}

// round 17
// speedup vs baseline: 1.6623x; 1.6623x over previous
#include <cuda_runtime.h>
#include <cuda_fp16.h>
#include <math.h>
#include <cstdint>

// ---------------------------------------------------------------------------
// Scratch
// ---------------------------------------------------------------------------
#define C0_OFF   0u
#define C1_OFF   6291456u
#define C2_OFF   7864320u
#define C3_OFF   8257536u
#define HI_OFF   8355840u                 // ushort[64*64*256] (hi, fp16)
#define HJ_OFF   9404416u                 // ushort[64*64*256] (hj, fp16)
#define SP_OFF   10452992u                // 4096*256 floats
#define WP_OFF   11501568u                // fp16 blob: 24*8192 ushorts = 384KB
#define SCRATCH_TOTAL 11698176u

__device__ float g_scratch[SCRATCH_TOTAL];

// ---------------------------------------------------------------------------
// Helpers
// ---------------------------------------------------------------------------
__device__ __forceinline__ uint32_t smem_u32(const void* p) {
    uint32_t a;
    asm("{ .reg .u64 t; cvta.to.shared.u64 t, %1; cvt.u32.u64 %0, t; }" : "=r"(a) : "l"(p));
    return a;
}

__device__ __forceinline__ void mma_f16(float& d0, float& d1, float& d2, float& d3,
                                        uint32_t a0, uint32_t a1, uint32_t a2, uint32_t a3,
                                        uint32_t b0, uint32_t b1) {
    asm volatile(
        "mma.sync.aligned.m16n8k16.row.col.f32.f16.f16.f32 "
        "{%0,%1,%2,%3},{%4,%5,%6,%7},{%8,%9},{%0,%1,%2,%3};"
        : "+f"(d0), "+f"(d1), "+f"(d2), "+f"(d3)
        : "r"(a0), "r"(a1), "r"(a2), "r"(a3), "r"(b0), "r"(b1));
}

#define LDSM_X4(r, addr) \
    asm volatile("ldmatrix.sync.aligned.m8n8.x4.shared.b16 {%0,%1,%2,%3}, [%4];" \
        : "=r"((r)[0]), "=r"((r)[1]), "=r"((r)[2]), "=r"((r)[3]) : "r"(addr))

// pack: low half = f16(v0), high half = f16(v1)
__device__ __forceinline__ uint32_t packh(float v0, float v1) {
    uint32_t r;
    asm("cvt.rn.f16x2.f32 %0, %1, %2;" : "=r"(r) : "f"(v1), "f"(v0));
    return r;
}

__device__ __forceinline__ uint32_t hadd2_relu(uint32_t a, uint32_t b) {
    uint32_t r;
    asm("{ .reg .b32 t; add.f16x2 t, %1, %2; max.f16x2 %0, t, %3; }"
        : "=r"(r) : "r"(a), "r"(b), "r"(0u));
    return r;
}

#define CP_ASYNC16(dst, src) \
    asm volatile("cp.async.cg.shared.global [%0], [%1], 16;" :: "r"(dst), "l"(src) : "memory")
#define CP_COMMIT() asm volatile("cp.async.commit_group;" ::: "memory")

// ---------------------------------------------------------------------------
// Slab-parallel Conv + BN + ReLU (R12/R14 proven configs, static smem)
// ---------------------------------------------------------------------------
template<int CIN, int W, int RPB, int CPT>
__global__ void __launch_bounds__(24 * RPB * (W / CPT)) conv_slab_kernel(
    const float* __restrict__ in, const float* __restrict__ w,
    const float* __restrict__ bns, const float* __restrict__ bnb,
    float* __restrict__ out, int Hin)
{
    constexpr int NT = 24 * RPB * (W / CPT);
    constexpr int R  = 2 * RPB + 1;
    constexpr int C  = 2 * W + 1;
    constexpr int Cp = 2 * W + 2;

    __shared__ float in_s[CIN * R * Cp];
    __shared__ float w_s[9 * CIN * 24];

    int t = threadIdx.x;
    constexpr int SLABS = W / RPB;
    int n    = blockIdx.x / SLABS;
    int slab = blockIdx.x % SLABS;
    int co   = t % 24;
    int rest = t / 24;
    int tcol = rest % (W / CPT);
    int orow = rest / (W / CPT);

    for (int l = t; l < 9 * CIN * 24; l += NT) w_s[l] = w[l];

    int ih0 = slab * RPB * 2 - 1;
    for (int l = t; l < CIN * R * C; l += NT) {
        int ci  = l / (R * C);
        int rem = l % (R * C);
        int r = rem / C, c = rem % C;
        int ih = ih0 + r, iw = c - 1;
        float v = 0.f;
        if (ih >= 0 && ih < Hin && iw >= 0 && iw < Hin)
            v = in[((n * CIN + ci) * Hin + ih) * Hin + iw];
        in_s[ci * (R * Cp) + r * Cp + c] = v;
    }
    __syncthreads();

    float acc[CPT];
#pragma unroll
    for (int o = 0; o < CPT; o++) acc[o] = 0.f;

#pragma unroll 2
    for (int ci = 0; ci < CIN; ci++) {
        float wr[9];
#pragma unroll
        for (int k = 0; k < 9; k++) wr[k] = w_s[k * (CIN * 24) + ci * 24 + co];
#pragma unroll
        for (int kh = 0; kh < 3; kh++) {
            const float* row = &in_s[ci * (R * Cp) + (orow * 2 + kh) * Cp + tcol * CPT * 2];
#pragma unroll
            for (int o = 0; o < CPT; o++) {
                acc[o] += wr[kh * 3 + 0] * row[2 * o];
                acc[o] += wr[kh * 3 + 1] * row[2 * o + 1];
                acc[o] += wr[kh * 3 + 2] * row[2 * o + 2];
            }
        }
    }

    float sc = bns[co], bb = bnb[co];
#pragma unroll
    for (int o = 0; o < CPT; o++) {
        float v = fmaxf(acc[o] * sc + bb, 0.f);
        out[((n * 24 + co) * W + slab * RPB + orow) * W + tcol * CPT + o] = v;
    }
}

// ---------------------------------------------------------------------------
// g layer 1: grid 256 (4 blocks per n, 16 p rows each). hi AND hj as fp16.
// ---------------------------------------------------------------------------
__global__ void __launch_bounds__(256) g1_kernel(
    const float* __restrict__ c3, const float* __restrict__ qst,
    const float* __restrict__ gw1, const float* __restrict__ gb1,
    unsigned short* __restrict__ hih, unsigned short* __restrict__ hjh)
{
    __shared__ float xs[64 * 26];
    __shared__ float qs[128];
    int n = blockIdx.x >> 2, pg = blockIdx.x & 3;
    int t = threadIdx.x;

    for (int l = t; l < 64 * 26; l += 256) {
        int p = l / 26, c = l % 26;
        int h = p >> 3, w = p & 7;
        float v;
        if (c < 24)       v = c3[((n * 24 + c) * 8 + h) * 8 + w];
        else if (c == 24) v = -1.f + (2.f / 7.f) * (float)w;
        else              v = -1.f + (2.f / 7.f) * (float)h;
        xs[l] = v;
    }
    if (t < 128) qs[t] = qst[n * 128 + t];
    __syncthreads();

    int o = t;
    float wa[26], wb[26];
#pragma unroll
    for (int c = 0; c < 26; c++) {
        wa[c] = gw1[c * 256 + o];
        wb[c] = gw1[(26 + c) * 256 + o];
    }
    float hq = gb1[o];
    for (int k = 0; k < 128; k++) hq += qs[k] * gw1[(52 + k) * 256 + o];

    for (int p = pg * 16; p < pg * 16 + 16; p++) {
        float ai = hq, bj = 0.f;
#pragma unroll
        for (int c = 0; c < 26; c++) {
            float x = xs[p * 26 + c];
            ai += x * wa[c];
            bj += x * wb[c];
        }
        __half ha = __float2half(ai);
        __half hb = __float2half(bj);
        hih[(n * 64 + p) * 256 + o] = *(unsigned short*)&ha;
        hjh[(n * 64 + p) * 256 + o] = *(unsigned short*)&hb;
    }
}

// ---------------------------------------------------------------------------
// Weight prep (R11 proven): stride-16 + XOR-swizzled fp16 blob.
// ---------------------------------------------------------------------------
__global__ void __launch_bounds__(256) prep_w_kernel(
    const float* __restrict__ w2, const float* __restrict__ w3,
    const float* __restrict__ w4, unsigned short* __restrict__ blob)
{
    int idx = blockIdx.x * 256 + threadIdx.x;      // 0..196607
    int l = idx >> 16;
    int rem = idx & 65535;
    int k = rem >> 8, n = rem & 255;
    const float* W = (l == 0) ? w2 : ((l == 1) ? w3 : w4);
    __half wh = __float2half(W[k * 256 + n]);

    int c   = k >> 5;
    int k2c = (k >> 1) & 15;
    int s   = k2c >> 3;
    int wi  = k2c & 7;
    int tt  = wi & 3;
    int j   = wi >> 2;
    int pos = tt * 4 + ((s ^ ((n >> 1) & 1)) * 2) + j;
    int gc  = l * 8 + c;
    blob[(size_t)gc * 8192 + (n * 16 + pos) * 2 + (k & 1)] = *(unsigned short*)&wh;
}

// ---------------------------------------------------------------------------
// fp16 mma relation MLP (R14 champion: 32KB double-buffered stages).
// Block = 64 pairs, 256 threads = 8 warps; warp tile 32M x 64N.
// SMEM words: A[0,8448)  W0[8448,16640) W1[16640,24832)  (32KB each, K=64)
//             bias[24832,25600) red[25600,26112)  -> 104448 bytes
// ---------------------------------------------------------------------------
extern __shared__ uint32_t smw[];

__device__ __forceinline__ void issue_pair(const char* __restrict__ blob,
                                           uint32_t wsm, int p, int tid)
{
    const char* src = blob + (size_t)p * 32768;
#pragma unroll
    for (int r = 0; r < 8; r++) {
        int op = r * 256 + tid;          // 0..2047, linear 32KB copy
        CP_ASYNC16(wsm + (uint32_t)(op * 16), src + op * 16);
    }
    CP_COMMIT();
}

__global__ void __launch_bounds__(256) rn_g_mma(
    const unsigned short* __restrict__ hih, const unsigned short* __restrict__ hjh,
    const unsigned short* __restrict__ wblob,
    const float* __restrict__ b2, const float* __restrict__ b3,
    const float* __restrict__ b4, float* __restrict__ spart)
{
    const char* blob = (const char*)wblob;
    int tid = threadIdx.x;
    int wid = tid >> 5, lane = tid & 31;
    int g = lane >> 2, t = lane & 3;
    int wm = wid & 1, wn = wid >> 1;
    uint32_t xg = (uint32_t)((g >> 1) & 1) << 1;   // B s-XOR offset (words)

    float* biasf = (float*)&smw[24832];
    float* red   = (float*)&smw[25600];
    uint32_t sb = smem_u32(smw);

    biasf[tid]       = b2[tid];
    biasf[256 + tid] = b3[tid];
    biasf[512 + tid] = b4[tid];

    // prologue: pair 0 (chunks 0,1) into buffer 0
    issue_pair(blob, sb + 33792u, 0, tid);

    // ---- L0: A = relu2(hi + hj), both already fp16 in gmem
    int nb = blockIdx.x >> 6;
    int ii = blockIdx.x & 63;
    {
        int m = tid >> 2, q = tid & 3;
        const uint32_t* hir = (const uint32_t*)(hih + (size_t)(nb * 64 + ii) * 256) + q * 32;
        const uint32_t* hjr = (const uint32_t*)(hjh + (size_t)(nb * 64 + m) * 256) + q * 32;
        int base = m * 132 + q * 32;
#pragma unroll 8
        for (int w = 0; w < 32; w++)
            smw[base + w] = hadd2_relu(hir[w], hjr[w]);
    }

    float acc[2][8][4];
    uint32_t abase0 = sb + (uint32_t)(((wm * 32 + (lane & 15)) * 132 + ((lane >> 4) << 2)) * 4);
    uint32_t abase1 = abase0 + 16u * 132u * 4u;

#pragma unroll 1
    for (int l = 0; l < 3; l++) {
#pragma unroll
        for (int mt = 0; mt < 2; mt++)
#pragma unroll
            for (int nt = 0; nt < 8; nt++)
#pragma unroll
                for (int q = 0; q < 4; q++) acc[mt][nt][q] = 0.f;

#pragma unroll 1
        for (int jj = 0; jj < 4; jj++) {
            int p = l * 4 + jj;                        // global stage 0..11
            asm volatile("cp.async.wait_group 0;" ::: "memory");
            __syncthreads();
            if (p < 11)
                issue_pair(blob, sb + 33792u + (uint32_t)((p + 1) & 1) * 32768u, p + 1, tid);

            uint32_t wbase = 8448u + (uint32_t)(p & 1) * 8192u;
#pragma unroll
            for (int sub = 0; sub < 2; sub++) {
                int c = 2 * jj + sub;                  // 0..7 within layer
                uint32_t wbw = wbase + (uint32_t)sub * 4096u;
                uint32_t coff = (uint32_t)c * 64u;     // A k-offset bytes

                uint32_t afr[2][2][4];
                LDSM_X4(afr[0][0], abase0 + coff);          // s0, strip0
                LDSM_X4(afr[0][1], abase1 + coff);          // s0, strip1
                LDSM_X4(afr[1][0], abase0 + coff + 32u);    // s1, strip0
                LDSM_X4(afr[1][1], abase1 + coff + 32u);    // s1, strip1

#pragma unroll
                for (int s = 0; s < 2; s++) {
                    uint32_t soff = ((uint32_t)s << 1) ^ xg;
#pragma unroll
                    for (int nt = 0; nt < 8; nt++) {
                        uint32_t wofs = wbw + (uint32_t)(((wn * 64 + nt * 8 + g) << 4) + (t << 2)) + soff;
                        uint2 B = *(const uint2*)&smw[wofs];
                        mma_f16(acc[0][nt][0], acc[0][nt][1], acc[0][nt][2], acc[0][nt][3],
                                afr[s][0][0], afr[s][0][1], afr[s][0][2], afr[s][0][3], B.x, B.y);
                        mma_f16(acc[1][nt][0], acc[1][nt][1], acc[1][nt][2], acc[1][nt][3],
                                afr[s][1][0], afr[s][1][1], afr[s][1][2], afr[s][1][3], B.x, B.y);
                    }
                }
            }
        }
        __syncthreads();   // all MMA reads of A done before epilogue overwrites A

        if (l < 2) {
#pragma unroll
            for (int mt = 0; mt < 2; mt++)
#pragma unroll
                for (int nt = 0; nt < 8; nt++) {
                    int n0 = wn * 64 + nt * 8 + 2 * t;
                    float2 bv = *(const float2*)&biasf[l * 256 + n0];
                    int nh = n0 >> 1;
                    int rbase = (wm * 32 + mt * 16 + g) * 132;
                    smw[rbase + nh] =
                        packh(fmaxf(acc[mt][nt][0] + bv.x, 0.f),
                              fmaxf(acc[mt][nt][1] + bv.y, 0.f));
                    smw[rbase + 1056 + nh] =
                        packh(fmaxf(acc[mt][nt][2] + bv.x, 0.f),
                              fmaxf(acc[mt][nt][3] + bv.y, 0.f));
                }
        } else {
#pragma unroll
            for (int nt = 0; nt < 8; nt++) {
                int n0 = wn * 64 + nt * 8 + 2 * t;
                float2 bv = *(const float2*)&biasf[512 + n0];
                float cs0 = fmaxf(acc[0][nt][0] + bv.x, 0.f) + fmaxf(acc[0][nt][2] + bv.x, 0.f)
                          + fmaxf(acc[1][nt][0] + bv.x, 0.f) + fmaxf(acc[1][nt][2] + bv.x, 0.f);
                float cs1 = fmaxf(acc[0][nt][1] + bv.y, 0.f) + fmaxf(acc[0][nt][3] + bv.y, 0.f)
                          + fmaxf(acc[1][nt][1] + bv.y, 0.f) + fmaxf(acc[1][nt][3] + bv.y, 0.f);
#pragma unroll
                for (int off = 16; off >= 4; off >>= 1) {
                    cs0 += __shfl_xor_sync(0xffffffffu, cs0, off);
                    cs1 += __shfl_xor_sync(0xffffffffu, cs1, off);
                }
                if (g == 0) {
                    red[wm * 256 + n0] = cs0;
                    red[wm * 256 + n0 + 1] = cs1;
                }
            }
            __syncthreads();
            float s = red[tid] + red[256 + tid];
            spart[(size_t)blockIdx.x * 256 + tid] = s;
        }
    }
}

// ---------------------------------------------------------------------------
// Reduce 64 partials per n, f-MLP + classifier + log_softmax (R13 version)
// ---------------------------------------------------------------------------
__global__ void __launch_bounds__(512) f_kernel(
    const float* __restrict__ spart,
    const float* __restrict__ fw1, const float* __restrict__ fb1,
    const float* __restrict__ fw2, const float* __restrict__ fb2,
    const float* __restrict__ cw,  const float* __restrict__ cb,
    float* __restrict__ out)
{
    __shared__ float a[256], b[256], part[512];
    int n = blockIdx.x, t = threadIdx.x;
    int hf = t >> 8, o = t & 255;

    const float* sp = spart + (size_t)(n * 64) * 256 + o;
    float v = 0.f;
    for (int i = hf * 32; i < hf * 32 + 32; i++) v += sp[i * 256];
    part[t] = v;
    __syncthreads();
    if (t < 256) a[t] = part[t] + part[t + 256];
    __syncthreads();

    float acc = 0.f;
    for (int k = 0; k < 128; k++)
        acc += a[hf * 128 + k] * fw1[(hf * 128 + k) * 256 + o];
    part[t] = acc;
    __syncthreads();
    if (t < 256) b[t] = fmaxf(part[t] + part[t + 256] + fb1[t], 0.f);
    __syncthreads();

    acc = 0.f;
    for (int k = 0; k < 128; k++)
        acc += b[hf * 128 + k] * fw2[(hf * 128 + k) * 256 + o];
    part[t] = acc;
    __syncthreads();
    if (t < 256) a[t] = fmaxf(part[t] + part[t + 256] + fb2[t], 0.f);
    __syncthreads();

    if (t < 32) {
        float lg = cb[t];
        for (int k = 0; k < 256; k++) lg += a[k] * cw[k * 32 + t];
        float mx = lg;
#pragma unroll
        for (int off = 16; off; off >>= 1)
            mx = fmaxf(mx, __shfl_xor_sync(0xffffffffu, mx, off));
        float e = expf(lg - mx);
        float se = e;
#pragma unroll
        for (int off = 16; off; off >>= 1)
            se += __shfl_xor_sync(0xffffffffu, se, off);
        out[(n << 5) + t] = lg - mx - logf(se);
    }
}

// ---------------------------------------------------------------------------
// Launch
// ---------------------------------------------------------------------------
extern "C" void kernel_launch(void* const* d_in, const int* in_sizes, int n_in,
                              void* d_out, int out_size)
{
    const float* img  = (const float*)d_in[0];
    const float* qst  = (const float*)d_in[1];
    const float* cw0  = (const float*)d_in[2];
    const float* cw1  = (const float*)d_in[3];
    const float* cw2  = (const float*)d_in[4];
    const float* cw3  = (const float*)d_in[5];
    const float* bs0  = (const float*)d_in[6];
    const float* bb0  = (const float*)d_in[7];
    const float* bs1  = (const float*)d_in[8];
    const float* bb1  = (const float*)d_in[9];
    const float* bs2  = (const float*)d_in[10];
    const float* bb2  = (const float*)d_in[11];
    const float* bs3  = (const float*)d_in[12];
    const float* bb3  = (const float*)d_in[13];
    const float* gw1  = (const float*)d_in[14];
    const float* gb1  = (const float*)d_in[15];
    const float* gw2  = (const float*)d_in[16];
    const float* gb2  = (const float*)d_in[17];
    const float* gw3  = (const float*)d_in[18];
    const float* gb3  = (const float*)d_in[19];
    const float* gw4  = (const float*)d_in[20];
    const float* gb4  = (const float*)d_in[21];
    const float* fw1  = (const float*)d_in[22];
    const float* fb1  = (const float*)d_in[23];
    const float* fw2  = (const float*)d_in[24];
    const float* fb2  = (const float*)d_in[25];
    const float* clw  = (const float*)d_in[26];
    const float* clb  = (const float*)d_in[27];
    float* out = (float*)d_out;

    void* base_v = nullptr;
    cudaGetSymbolAddress(&base_v, g_scratch);
    float* base = (float*)base_v;
    float* c0 = base + C0_OFF;
    float* c1 = base + C1_OFF;
    float* c2 = base + C2_OFF;
    float* c3 = base + C3_OFF;
    unsigned short* hih = (unsigned short*)(base + HI_OFF);
    unsigned short* hjh = (unsigned short*)(base + HJ_OFF);
    float* sp = base + SP_OFF;
    unsigned short* wp = (unsigned short*)(base + WP_OFF);

    cudaFuncSetAttribute(rn_g_mma, cudaFuncAttributeMaxDynamicSharedMemorySize, 104448);

    prep_w_kernel<<<768, 256>>>(gw2, gw3, gw4, wp);

    conv_slab_kernel<3, 64, 1, 8><<<4096, 192>>>(img, cw0, bs0, bb0, c0, 128);
    conv_slab_kernel<24, 32, 1, 4><<<2048, 192>>>(c0, cw1, bs1, bb1, c1, 64);
    conv_slab_kernel<24, 16, 2, 4><<<512, 192>>>(c1, cw2, bs2, bb2, c2, 32);
    conv_slab_kernel<24, 8, 4, 4><<<128, 192>>>(c2, cw3, bs3, bb3, c3, 16);

    g1_kernel<<<256, 256>>>(c3, qst, gw1, gb1, hih, hjh);

    rn_g_mma<<<4096, 256, 104448>>>(hih, hjh, wp, gb2, gb3, gb4, sp);

    f_kernel<<<64, 512>>>(sp, fw1, fb1, fw2, fb2, clw, clb, out);
}